// round 9
// baseline (speedup 1.0000x reference)
#include <cuda_runtime.h>
#include <cuda_bf16.h>
#include <cstdint>

// Problem constants
#define BATCH 4
#define SEQ   2048
#define HID   768
#define NHEAD 12
#define HDIM  64
#define QKV3  2304
#define KDIM  768

// Scratch (allocation-free: __device__ globals)
__device__ float g_qkv[(long)BATCH * SEQ * QKV3];    // [B,S,3H] tf32-rounded
__device__ float g_attn[(long)BATCH * SEQ * HID];    // [B,S,H]  tf32-rounded
__device__ float g_xc[(long)BATCH * SEQ * HID];      // x, tf32-rounded
__device__ float g_wqkvc[(long)KDIM * QKV3];         // w_qkv tf32-rounded [K][N]
__device__ float g_woutc[(long)KDIM * HID];          // w_out tf32-rounded [K][N]

// ---------------------------------------------------------------------------
// Helpers
// ---------------------------------------------------------------------------
__device__ __forceinline__ uint32_t smem_u32(const void* p) {
    uint32_t a;
    asm("{ .reg .u64 t; cvta.to.shared.u64 t, %1; cvt.u32.u64 %0, t; }" : "=r"(a) : "l"(p));
    return a;
}
__device__ __forceinline__ float cvt_tf32(float x) {
    float r;
    asm("cvt.rna.tf32.f32 %0, %1;" : "=f"(r) : "f"(x));
    return r;
}
__device__ __forceinline__ float ex2f(float x) {
    float r;
    asm("ex2.approx.f32 %0, %1;" : "=f"(r) : "f"(x));
    return r;
}
__device__ __forceinline__ void cp16(uint32_t dst, const void* src) {
    asm volatile("cp.async.cg.shared.global [%0], [%1], 16;" :: "r"(dst), "l"(src) : "memory");
}
__device__ __forceinline__ void cp_commit() {
    asm volatile("cp.async.commit_group;" ::: "memory");
}
__device__ __forceinline__ void cp_wait1() {
    asm volatile("cp.async.wait_group 1;" ::: "memory");
}
__device__ __forceinline__ void cp_wait0() {
    asm volatile("cp.async.wait_group 0;" ::: "memory");
}
__device__ __forceinline__ uint32_t ldsu(uint32_t addr) {
    uint32_t v;
    asm volatile("ld.shared.b32 %0, [%1];" : "=r"(v) : "r"(addr));
    return v;
}
__device__ __forceinline__ void sts2(uint32_t addr, float x, float y) {
    asm volatile("st.shared.v2.f32 [%0], {%1, %2};" :: "r"(addr), "f"(x), "f"(y) : "memory");
}
__device__ __forceinline__ void mma_tf32(float* c, const uint32_t* a, const uint32_t* b) {
    asm volatile(
        "mma.sync.aligned.m16n8k8.row.col.f32.tf32.tf32.f32 "
        "{%0,%1,%2,%3}, {%4,%5,%6,%7}, {%8,%9}, {%0,%1,%2,%3};"
        : "+f"(c[0]), "+f"(c[1]), "+f"(c[2]), "+f"(c[3])
        : "r"(a[0]), "r"(a[1]), "r"(a[2]), "r"(a[3]), "r"(b[0]), "r"(b[1]));
}

// ---------------------------------------------------------------------------
// tf32 mma.sync GEMM, v3: 3-stage cp.async pipeline + register double-buffered
// fragments. launch_bounds(256,1): allow >128 regs so the double buffer is
// actually materialized (at (256,2) ptxas serialized it).
// ---------------------------------------------------------------------------
#define AS_BYTES (128 * 36 * 4)   // 18432, A row pitch 144B
#define BS_BYTES (32 * 132 * 4)   // 16896, B row pitch 528B
#define STAGE_BYTES (AS_BYTES + BS_BYTES)
#define GEMM_SMEM_BYTES (3 * STAGE_BYTES)   // 105984

template <bool ROUND>
__global__ __launch_bounds__(256, 1)
void gemm_tf32(const float* __restrict__ A, const float* __restrict__ B,
               float* __restrict__ C, int M, int N, int K)
{
    extern __shared__ char smem[];
    const uint32_t sb = smem_u32(smem);

    const int tid = threadIdx.x;
    const int wid = tid >> 5, lane = tid & 31;
    const int g = lane >> 2, l4 = lane & 3;
    const int warpM = wid >> 2, warpN = wid & 3;
    const int m0 = blockIdx.y * 128, n0 = blockIdx.x * 128;

    const int ar = tid >> 1;
    const int ah = (tid & 1) * 64;
    const int bkr = tid >> 3;
    const int bseg = (tid & 7) * 64;

    const float* Ag = A + (long)(m0 + ar) * K;
    const float* Bg = B + n0;
    const int nch = K / 32;

    float c[4][4][4];
    #pragma unroll
    for (int mt = 0; mt < 4; mt++)
        #pragma unroll
        for (int nt = 0; nt < 4; nt++)
            #pragma unroll
            for (int r = 0; r < 4; r++) c[mt][nt][r] = 0.f;

    auto issue = [&](int chunk, int s) {
        const int k0 = chunk * 32;
        const uint32_t stage = sb + (uint32_t)s * STAGE_BYTES;
        const float* asrc = Ag + k0 + (ah >> 2);
        uint32_t adst = stage + ar * 144 + ah;
        #pragma unroll
        for (int q = 0; q < 4; q++) cp16(adst + q * 16, asrc + q * 4);
        const float* bsrc = Bg + (long)(k0 + bkr) * N + (bseg >> 2);
        uint32_t bdst = stage + AS_BYTES + bkr * 528 + bseg;
        #pragma unroll
        for (int q = 0; q < 4; q++) cp16(bdst + q * 16, bsrc + q * 4);
    };

    issue(0, 0); cp_commit();
    issue(1, 1); cp_commit();

    const uint32_t aoff = (uint32_t)((warpM * 64 + g) * 144 + l4 * 4);
    const uint32_t boff = (uint32_t)(AS_BYTES + l4 * 528 + (warpN * 32 + g) * 4);

    uint32_t af[2][4][4], bf[2][4][2];

    #pragma unroll 1
    for (int i = 0; i < nch; i++) {
        const int s = i - (i / 3) * 3;
        if (i + 1 < nch) cp_wait1(); else cp_wait0();
        __syncthreads();
        if (i + 2 < nch) { issue(i + 2, (i + 2) % 3); cp_commit(); }

        const uint32_t abase = sb + (uint32_t)s * STAGE_BYTES + aoff;
        const uint32_t bbase = sb + (uint32_t)s * STAGE_BYTES + boff;

        #pragma unroll
        for (int mt = 0; mt < 4; mt++) {
            const uint32_t a = abase + mt * (16 * 144);
            af[0][mt][0] = ldsu(a);
            af[0][mt][1] = ldsu(a + 8 * 144);
            af[0][mt][2] = ldsu(a + 16);
            af[0][mt][3] = ldsu(a + 8 * 144 + 16);
        }
        #pragma unroll
        for (int nt = 0; nt < 4; nt++) {
            const uint32_t a = bbase + nt * 32;
            bf[0][nt][0] = ldsu(a);
            bf[0][nt][1] = ldsu(a + 4 * 528);
        }

        #pragma unroll
        for (int ks = 0; ks < 4; ks++) {
            const int cur = ks & 1, nxt = cur ^ 1;
            if (ks < 3) {
                #pragma unroll
                for (int mt = 0; mt < 4; mt++) {
                    const uint32_t a = abase + mt * (16 * 144) + (ks + 1) * 32;
                    af[nxt][mt][0] = ldsu(a);
                    af[nxt][mt][1] = ldsu(a + 8 * 144);
                    af[nxt][mt][2] = ldsu(a + 16);
                    af[nxt][mt][3] = ldsu(a + 8 * 144 + 16);
                }
                #pragma unroll
                for (int nt = 0; nt < 4; nt++) {
                    const uint32_t a = bbase + (ks + 1) * (8 * 528) + nt * 32;
                    bf[nxt][nt][0] = ldsu(a);
                    bf[nxt][nt][1] = ldsu(a + 4 * 528);
                }
            }
            #pragma unroll
            for (int mt = 0; mt < 4; mt++)
                #pragma unroll
                for (int nt = 0; nt < 4; nt++)
                    mma_tf32(c[mt][nt], af[cur][mt], bf[cur][nt]);
        }
    }

    #pragma unroll
    for (int mt = 0; mt < 4; mt++) {
        #pragma unroll
        for (int nt = 0; nt < 4; nt++) {
            const long row0 = (long)(m0 + warpM * 64 + mt * 16 + g);
            const int col = n0 + warpN * 32 + nt * 8 + l4 * 2;
            float v0 = c[mt][nt][0], v1 = c[mt][nt][1];
            float v2 = c[mt][nt][2], v3 = c[mt][nt][3];
            if (ROUND) {
                v0 = cvt_tf32(v0); v1 = cvt_tf32(v1);
                v2 = cvt_tf32(v2); v3 = cvt_tf32(v3);
            }
            *(float2*)&C[row0 * N + col] = make_float2(v0, v1);
            *(float2*)&C[(row0 + 8) * N + col] = make_float2(v2, v3);
        }
    }
}

// ---------------------------------------------------------------------------
// Elementwise tf32 rounding (prep)
// ---------------------------------------------------------------------------
__global__ void cvt_tf32_kernel(const float* __restrict__ in, float* __restrict__ out,
                                int n4)
{
    int i = blockIdx.x * blockDim.x + threadIdx.x;
    if (i < n4) {
        float4 v = ((const float4*)in)[i];
        v.x = cvt_tf32(v.x); v.y = cvt_tf32(v.y);
        v.z = cvt_tf32(v.z); v.w = cvt_tf32(v.w);
        ((float4*)out)[i] = v;
    }
}

// ---------------------------------------------------------------------------
// Flash attention (causal) on tf32 mma.sync, v2: 256 threads / 8 warps.
// Each warp owns 16 q-rows of the 128-row tile (was 32 rows / 4 warps).
// Same fragment mappings as v1 with the mt dimension removed.
// ---------------------------------------------------------------------------
#define FQT 128
#define FKT 64
#define KP 68
#define VP 72
#define PP 68
#define KS_OFF(s)  ((s) * 17408)
#define VS_OFF(s)  (34816 + (s) * 18432)
#define PS_OFF     71680
#define FLASH_SMEM_BYTES (PS_OFF + 128 * PP * 4)   // 106496
#define SC2 0.1803368801f   // (1/sqrt(64)) * log2(e)

__global__ __launch_bounds__(256)
void flash_tf32(const float* __restrict__ qkv, float* __restrict__ out)
{
    extern __shared__ char sm[];
    const uint32_t sb = smem_u32(sm);
    const int tid = threadIdx.x, w = tid >> 5, lane = tid & 31;
    const int g = lane >> 2, l4 = lane & 3;
    const int qt = (int)(gridDim.x - 1) - (int)blockIdx.x;   // heavy blocks first
    const int hh = blockIdx.y, b = blockIdx.z;
    const int q0 = qt * FQT;
    const int nkv = 2 * qt + 2;

    const float* qg = qkv + (long)b * SEQ * QKV3 + hh * HDIM;
    const float* kg = qg + HID;
    const float* vg = qg + 2 * HID;

    // --- Stage Q into PS region [128][PP]: 256 threads x 32 floats = 8192 ---
    {
        const int r = tid >> 1, h2 = tid & 1;
        const float* src = qg + (long)(q0 + r) * QKV3 + h2 * 32;
        uint32_t dst = sb + PS_OFF + (uint32_t)(r * PP + h2 * 32) * 4;
        #pragma unroll
        for (int q = 0; q < 8; q++) cp16(dst + q * 16, src + q * 4);
        cp_commit();
    }
    cp_wait0();
    __syncthreads();

    // --- Q fragments: warp rows [w*16, w*16+16) ---
    uint32_t qa[8][4];
    #pragma unroll
    for (int ks = 0; ks < 8; ks++) {
        uint32_t base = sb + PS_OFF
            + (uint32_t)((w * 16 + g) * PP + ks * 8 + l4) * 4;
        qa[ks][0] = ldsu(base);
        qa[ks][1] = ldsu(base + 8 * PP * 4);
        qa[ks][2] = ldsu(base + 16);
        qa[ks][3] = ldsu(base + 8 * PP * 4 + 16);
    }
    __syncthreads();

    // KV loader: 256 threads, 64 rows x 64 floats -> 16 floats (4x cp16) each
    auto issue_kv = [&](int kt2, int s) {
        const int k0 = kt2 * FKT;
        const int r = tid >> 2, q4 = tid & 3;
        const float* ksrc = kg + (long)(k0 + r) * QKV3 + q4 * 16;
        uint32_t kdst = sb + KS_OFF(s) + (uint32_t)(r * KP + q4 * 16) * 4;
        #pragma unroll
        for (int q = 0; q < 4; q++) cp16(kdst + q * 16, ksrc + q * 4);
        const float* vsrc = vg + (long)(k0 + r) * QKV3 + q4 * 16;
        uint32_t vdst = sb + VS_OFF(s) + (uint32_t)(r * VP + q4 * 16) * 4;
        #pragma unroll
        for (int q = 0; q < 4; q++) cp16(vdst + q * 16, vsrc + q * 4);
    };

    issue_kv(0, 0); cp_commit();
    if (nkv > 1) issue_kv(1, 1);
    cp_commit();

    float mA = -1e30f, mB = -1e30f, lA = 0.f, lB = 0.f;
    float o[8][4];
    #pragma unroll
    for (int nt = 0; nt < 8; nt++)
        #pragma unroll
        for (int r = 0; r < 4; r++) o[nt][r] = 0.f;

    const int wrow0 = q0 + w * 16;

    #pragma unroll 1
    for (int kt = 0; kt < nkv; kt++) {
        const int s = kt & 1;
        if (kt + 2 < nkv) cp_wait1(); else cp_wait0();
        __syncthreads();

        const int k0 = kt * FKT;
        const bool active = (k0 <= wrow0 + 15);
        const bool needmask = (k0 + FKT - 1 > wrow0);

        if (active) {
            const uint32_t kb = sb + KS_OFF(s);
            const uint32_t vb = sb + VS_OFF(s);

            float cc[8][4];
            #pragma unroll
            for (int nt = 0; nt < 8; nt++)
                #pragma unroll
                for (int r = 0; r < 4; r++) cc[nt][r] = 0.f;

            // S = Q @ K^T
            #pragma unroll
            for (int ks = 0; ks < 8; ks++) {
                uint32_t bfr[8][2];
                #pragma unroll
                for (int nt = 0; nt < 8; nt++) {
                    uint32_t a = kb + (uint32_t)((nt * 8 + g) * KP + ks * 8 + l4) * 4;
                    bfr[nt][0] = ldsu(a);
                    bfr[nt][1] = ldsu(a + 16);
                }
                #pragma unroll
                for (int nt = 0; nt < 8; nt++)
                    mma_tf32(cc[nt], qa[ks], bfr[nt]);
            }

            const int rowA = wrow0 + g;
            if (needmask) {
                #pragma unroll
                for (int nt = 0; nt < 8; nt++) {
                    const int colb = k0 + nt * 8 + 2 * l4;
                    if (colb     > rowA)     cc[nt][0] = -1e30f;
                    if (colb + 1 > rowA)     cc[nt][1] = -1e30f;
                    if (colb     > rowA + 8) cc[nt][2] = -1e30f;
                    if (colb + 1 > rowA + 8) cc[nt][3] = -1e30f;
                }
            }

            // online softmax (rows A: regs 0,1 ; rows B: regs 2,3)
            float mxA = -1e30f, mxB = -1e30f;
            #pragma unroll
            for (int nt = 0; nt < 8; nt++) {
                mxA = fmaxf(mxA, fmaxf(cc[nt][0], cc[nt][1]));
                mxB = fmaxf(mxB, fmaxf(cc[nt][2], cc[nt][3]));
            }
            mxA = fmaxf(mxA, __shfl_xor_sync(0xffffffffu, mxA, 1));
            mxA = fmaxf(mxA, __shfl_xor_sync(0xffffffffu, mxA, 2));
            mxB = fmaxf(mxB, __shfl_xor_sync(0xffffffffu, mxB, 1));
            mxB = fmaxf(mxB, __shfl_xor_sync(0xffffffffu, mxB, 2));

            const float mAn = fmaxf(mA, mxA);
            const float mBn = fmaxf(mB, mxB);
            const float aAl = ex2f((mA - mAn) * SC2);
            const float aBl = ex2f((mB - mBn) * SC2);
            mA = mAn; mB = mBn;

            float sA = 0.f, sB = 0.f;
            const uint32_t pbase = sb + PS_OFF
                + (uint32_t)((w * 16 + g) * PP + 2 * l4) * 4;
            #pragma unroll
            for (int nt = 0; nt < 8; nt++) {
                float p0 = ex2f((cc[nt][0] - mAn) * SC2);
                float p1 = ex2f((cc[nt][1] - mAn) * SC2);
                float p2 = ex2f((cc[nt][2] - mBn) * SC2);
                float p3 = ex2f((cc[nt][3] - mBn) * SC2);
                sA += p0 + p1; sB += p2 + p3;
                sts2(pbase + nt * 32, cvt_tf32(p0), cvt_tf32(p1));
                sts2(pbase + nt * 32 + 8 * PP * 4, cvt_tf32(p2), cvt_tf32(p3));
            }
            sA += __shfl_xor_sync(0xffffffffu, sA, 1);
            sA += __shfl_xor_sync(0xffffffffu, sA, 2);
            sB += __shfl_xor_sync(0xffffffffu, sB, 1);
            sB += __shfl_xor_sync(0xffffffffu, sB, 2);
            lA = lA * aAl + sA;
            lB = lB * aBl + sB;

            #pragma unroll
            for (int nt = 0; nt < 8; nt++) {
                o[nt][0] *= aAl; o[nt][1] *= aAl;
                o[nt][2] *= aBl; o[nt][3] *= aBl;
            }
            __syncwarp();

            // O += P @ V (each warp reads only its own 16 P rows)
            #pragma unroll
            for (int ks = 0; ks < 8; ks++) {
                uint32_t pa[4];
                {
                    uint32_t base = sb + PS_OFF
                        + (uint32_t)((w * 16 + g) * PP + ks * 8 + l4) * 4;
                    pa[0] = ldsu(base);
                    pa[1] = ldsu(base + 8 * PP * 4);
                    pa[2] = ldsu(base + 16);
                    pa[3] = ldsu(base + 8 * PP * 4 + 16);
                }
                uint32_t bv[8][2];
                #pragma unroll
                for (int nt = 0; nt < 8; nt++) {
                    uint32_t a = vb + (uint32_t)((ks * 8 + l4) * VP + nt * 8 + g) * 4;
                    bv[nt][0] = ldsu(a);
                    bv[nt][1] = ldsu(a + 4 * VP * 4);
                }
                #pragma unroll
                for (int nt = 0; nt < 8; nt++)
                    mma_tf32(o[nt], pa, bv[nt]);
            }
        }

        __syncthreads();
        if (kt + 2 < nkv) { issue_kv(kt + 2, s); cp_commit(); }
    }

    // Epilogue: normalize, tf32-round, write [B,S,H]
    {
        const float invA = 1.f / lA;
        const float invB = 1.f / lB;
        const long rowA = (long)b * SEQ + q0 + w * 16 + g;
        #pragma unroll
        for (int nt = 0; nt < 8; nt++) {
            const int col = hh * HDIM + nt * 8 + 2 * l4;
            *(float2*)&out[rowA * HID + col] =
                make_float2(cvt_tf32(o[nt][0] * invA), cvt_tf32(o[nt][1] * invA));
            *(float2*)&out[(rowA + 8) * HID + col] =
                make_float2(cvt_tf32(o[nt][2] * invB), cvt_tf32(o[nt][3] * invB));
        }
    }
}

// ---------------------------------------------------------------------------
// Launch
// ---------------------------------------------------------------------------
extern "C" void kernel_launch(void* const* d_in, const int* in_sizes, int n_in,
                              void* d_out, int out_size)
{
    const float* x     = (const float*)d_in[0];
    const float* w_qkv = (const float*)d_in[1];
    const float* w_out = (const float*)d_in[2];
    float* out = (float*)d_out;

    float *qkv, *attn, *xc, *wqkvc, *woutc;
    cudaGetSymbolAddress((void**)&qkv, g_qkv);
    cudaGetSymbolAddress((void**)&attn, g_attn);
    cudaGetSymbolAddress((void**)&xc, g_xc);
    cudaGetSymbolAddress((void**)&wqkvc, g_wqkvc);
    cudaGetSymbolAddress((void**)&woutc, g_woutc);

    const int M = BATCH * SEQ;   // 8192

    // 0) tf32-round GEMM inputs
    {
        int n4 = (M * HID) / 4;
        cvt_tf32_kernel<<<(n4 + 255) / 256, 256>>>(x, xc, n4);
        n4 = (KDIM * QKV3) / 4;
        cvt_tf32_kernel<<<(n4 + 255) / 256, 256>>>(w_qkv, wqkvc, n4);
        n4 = (KDIM * HID) / 4;
        cvt_tf32_kernel<<<(n4 + 255) / 256, 256>>>(w_out, woutc, n4);
    }

    cudaFuncSetAttribute(gemm_tf32<true>, cudaFuncAttributeMaxDynamicSharedMemorySize,
                         GEMM_SMEM_BYTES);
    cudaFuncSetAttribute(gemm_tf32<false>, cudaFuncAttributeMaxDynamicSharedMemorySize,
                         GEMM_SMEM_BYTES);
    cudaFuncSetAttribute(flash_tf32, cudaFuncAttributeMaxDynamicSharedMemorySize,
                         FLASH_SMEM_BYTES);

    // 1) QKV projection (output tf32-rounded for the attention mma)
    gemm_tf32<true><<<dim3(QKV3 / 128, M / 128), 256, GEMM_SMEM_BYTES>>>(
        xc, wqkvc, qkv, M, QKV3, KDIM);

    // 2) Causal flash attention on tensor cores (8 warps/block)
    flash_tf32<<<dim3(SEQ / FQT, NHEAD, BATCH), 256, FLASH_SMEM_BYTES>>>(qkv, attn);

    // 3) Output projection
    gemm_tf32<false><<<dim3(HID / 128, M / 128), 256, GEMM_SMEM_BYTES>>>(
        attn, woutc, out, M, HID, KDIM);
}

// round 10
// speedup vs baseline: 1.0996x; 1.0996x over previous
#include <cuda_runtime.h>
#include <cuda_bf16.h>
#include <cstdint>

// Problem constants
#define BATCH 4
#define SEQ   2048
#define HID   768
#define NHEAD 12
#define HDIM  64
#define QKV3  2304
#define KDIM  768

// Scratch (allocation-free: __device__ globals)
__device__ float g_qkv[(long)BATCH * SEQ * QKV3];    // [B,S,3H] tf32-rounded
__device__ float g_attn[(long)BATCH * SEQ * HID];    // [B,S,H]  tf32-rounded
__device__ float g_xc[(long)BATCH * SEQ * HID];      // x, tf32-rounded
__device__ float g_wqkvT[(long)QKV3 * KDIM];         // w_qkv tf32-rounded, [N][K]
__device__ float g_woutT[(long)HID * KDIM];          // w_out tf32-rounded, [N][K]

// ---------------------------------------------------------------------------
// Helpers
// ---------------------------------------------------------------------------
__device__ __forceinline__ uint32_t smem_u32(const void* p) {
    uint32_t a;
    asm("{ .reg .u64 t; cvta.to.shared.u64 t, %1; cvt.u32.u64 %0, t; }" : "=r"(a) : "l"(p));
    return a;
}
__device__ __forceinline__ float cvt_tf32(float x) {
    float r;
    asm("cvt.rna.tf32.f32 %0, %1;" : "=f"(r) : "f"(x));
    return r;
}
__device__ __forceinline__ float ex2f(float x) {
    float r;
    asm("ex2.approx.f32 %0, %1;" : "=f"(r) : "f"(x));
    return r;
}
__device__ __forceinline__ void cp16(uint32_t dst, const void* src) {
    asm volatile("cp.async.cg.shared.global [%0], [%1], 16;" :: "r"(dst), "l"(src) : "memory");
}
__device__ __forceinline__ void cp_commit() {
    asm volatile("cp.async.commit_group;" ::: "memory");
}
__device__ __forceinline__ void cp_wait1() {
    asm volatile("cp.async.wait_group 1;" ::: "memory");
}
__device__ __forceinline__ void cp_wait0() {
    asm volatile("cp.async.wait_group 0;" ::: "memory");
}
__device__ __forceinline__ uint32_t ldsu(uint32_t addr) {
    uint32_t v;
    asm volatile("ld.shared.b32 %0, [%1];" : "=r"(v) : "r"(addr));
    return v;
}
__device__ __forceinline__ void sts2(uint32_t addr, float x, float y) {
    asm volatile("st.shared.v2.f32 [%0], {%1, %2};" :: "r"(addr), "f"(x), "f"(y) : "memory");
}
__device__ __forceinline__ void ldsm4(uint32_t* r, uint32_t addr) {
    asm volatile("ldmatrix.sync.aligned.m8n8.x4.shared.b16 {%0,%1,%2,%3}, [%4];"
                 : "=r"(r[0]), "=r"(r[1]), "=r"(r[2]), "=r"(r[3]) : "r"(addr));
}
__device__ __forceinline__ void ldsm2(uint32_t* r, uint32_t addr) {
    asm volatile("ldmatrix.sync.aligned.m8n8.x2.shared.b16 {%0,%1}, [%2];"
                 : "=r"(r[0]), "=r"(r[1]) : "r"(addr));
}
__device__ __forceinline__ void mma_tf32(float* c, const uint32_t* a, const uint32_t* b) {
    asm volatile(
        "mma.sync.aligned.m16n8k8.row.col.f32.tf32.tf32.f32 "
        "{%0,%1,%2,%3}, {%4,%5,%6,%7}, {%8,%9}, {%0,%1,%2,%3};"
        : "+f"(c[0]), "+f"(c[1]), "+f"(c[2]), "+f"(c[3])
        : "r"(a[0]), "r"(a[1]), "r"(a[2]), "r"(a[3]), "r"(b[0]), "r"(b[1]));
}

// ---------------------------------------------------------------------------
// tf32 mma.sync GEMM v4: ldmatrix fragment loads.
// C[M,N] = A[M,K] @ Bt[N,K]^T (Bt row-major [N][K], pre-transposed weights).
// CTA 128x128, K chunk 32, 3-stage cp.async (1 sync/chunk), 8 warps (2Mx4N).
// SMEM per stage: As[128][36f] + Bs[128][36f], both 144B pitch (conflict-free
// for ldmatrix: 8-row phases hit distinct 16B groups since 9r mod 8 distinct).
// ROUND: tf32-round output (for qkv feeding the attention mma).
// ---------------------------------------------------------------------------
#define AT_BYTES (128 * 36 * 4)   // 18432
#define STAGE_BYTES (2 * AT_BYTES)   // 36864 (A then B)
#define GEMM_SMEM_BYTES (3 * STAGE_BYTES)   // 110592

template <bool ROUND>
__global__ __launch_bounds__(256, 2)
void gemm_tf32(const float* __restrict__ A, const float* __restrict__ Bt,
               float* __restrict__ C, int M, int N, int K)
{
    extern __shared__ char smem[];
    const uint32_t sb = smem_u32(smem);

    const int tid = threadIdx.x;
    const int wid = tid >> 5, lane = tid & 31;
    const int g = lane >> 2, l4 = lane & 3;
    const int warpM = wid >> 2, warpN = wid & 3;
    const int m0 = blockIdx.y * 128, n0 = blockIdx.x * 128;

    // cp.async mapping: both tiles are 128 rows x 128B
    const int r = tid >> 1;
    const int h = (tid & 1) * 64;   // byte offset of 64B half

    const float* Ag = A + (long)(m0 + r) * K + (h >> 2);
    const float* Bg = Bt + (long)(n0 + r) * K + (h >> 2);
    const int nch = K / 32;

    float c[4][4][4];
    #pragma unroll
    for (int mt = 0; mt < 4; mt++)
        #pragma unroll
        for (int nt = 0; nt < 4; nt++)
            #pragma unroll
            for (int q = 0; q < 4; q++) c[mt][nt][q] = 0.f;

    auto issue = [&](int chunk, int s) {
        const int k0 = chunk * 32;
        const uint32_t stage = sb + (uint32_t)s * STAGE_BYTES;
        const uint32_t dst = stage + r * 144 + h;
        const float* asrc = Ag + k0;
        #pragma unroll
        for (int q = 0; q < 4; q++) cp16(dst + q * 16, asrc + q * 4);
        const float* bsrc = Bg + k0;
        #pragma unroll
        for (int q = 0; q < 4; q++) cp16(dst + AT_BYTES + q * 16, bsrc + q * 4);
    };

    issue(0, 0); cp_commit();
    issue(1, 1); cp_commit();

    // ldmatrix lane address components
    const int rlm = lane & 15, half = (lane >> 4) * 16;          // A: x4
    const int nr = lane & 7, sel = ((lane >> 3) & 1) * 16;       // B: x2
    const uint32_t aoff = (uint32_t)((warpM * 64 + rlm) * 144 + half);
    const uint32_t boff = (uint32_t)(AT_BYTES + (warpN * 32 + nr) * 144 + sel);

    #pragma unroll 1
    for (int i = 0; i < nch; i++) {
        const int s = i - (i / 3) * 3;
        if (i + 1 < nch) cp_wait1(); else cp_wait0();
        __syncthreads();
        if (i + 2 < nch) { issue(i + 2, (i + 2) % 3); cp_commit(); }

        const uint32_t abase = sb + (uint32_t)s * STAGE_BYTES + aoff;
        const uint32_t bbase = sb + (uint32_t)s * STAGE_BYTES + boff;

        #pragma unroll
        for (int ks = 0; ks < 4; ks++) {
            uint32_t af[4][4], bf[4][2];
            #pragma unroll
            for (int mt = 0; mt < 4; mt++)
                ldsm4(af[mt], abase + mt * (16 * 144) + ks * 32);
            #pragma unroll
            for (int nt = 0; nt < 4; nt++)
                ldsm2(bf[nt], bbase + nt * (8 * 144) + ks * 32);
            #pragma unroll
            for (int mt = 0; mt < 4; mt++)
                #pragma unroll
                for (int nt = 0; nt < 4; nt++)
                    mma_tf32(c[mt][nt], af[mt], bf[nt]);
        }
    }

    #pragma unroll
    for (int mt = 0; mt < 4; mt++) {
        #pragma unroll
        for (int nt = 0; nt < 4; nt++) {
            const long row0 = (long)(m0 + warpM * 64 + mt * 16 + g);
            const int col = n0 + warpN * 32 + nt * 8 + l4 * 2;
            float v0 = c[mt][nt][0], v1 = c[mt][nt][1];
            float v2 = c[mt][nt][2], v3 = c[mt][nt][3];
            if (ROUND) {
                v0 = cvt_tf32(v0); v1 = cvt_tf32(v1);
                v2 = cvt_tf32(v2); v3 = cvt_tf32(v3);
            }
            *(float2*)&C[row0 * N + col] = make_float2(v0, v1);
            *(float2*)&C[(row0 + 8) * N + col] = make_float2(v2, v3);
        }
    }
}

// ---------------------------------------------------------------------------
// Prep kernels
// ---------------------------------------------------------------------------
__global__ void cvt_tf32_kernel(const float* __restrict__ in, float* __restrict__ out,
                                int n4)
{
    int i = blockIdx.x * blockDim.x + threadIdx.x;
    if (i < n4) {
        float4 v = ((const float4*)in)[i];
        v.x = cvt_tf32(v.x); v.y = cvt_tf32(v.y);
        v.z = cvt_tf32(v.z); v.w = cvt_tf32(v.w);
        ((float4*)out)[i] = v;
    }
}

// out[c][r] = tf32(in[r][c]).  in: [R][C] row-major, out: [C][R] row-major.
__global__ void transpose_tf32(const float* __restrict__ in, float* __restrict__ out,
                               int R, int C)
{
    __shared__ float tile[32][33];
    const int c0 = blockIdx.x * 32, r0 = blockIdx.y * 32;
    const int tx = threadIdx.x, ty = threadIdx.y;
    #pragma unroll
    for (int j = ty; j < 32; j += 8)
        tile[j][tx] = in[(long)(r0 + j) * C + c0 + tx];
    __syncthreads();
    #pragma unroll
    for (int j = ty; j < 32; j += 8)
        out[(long)(c0 + j) * R + r0 + tx] = cvt_tf32(tile[tx][j]);
}

// ---------------------------------------------------------------------------
// Flash attention (causal) on tf32 mma.sync — R9 version (passing), unchanged.
// 256 threads / 8 warps; warp w owns 16 q-rows.
// ---------------------------------------------------------------------------
#define FQT 128
#define FKT 64
#define KP 68
#define VP 72
#define PP 68
#define KS_OFF(s)  ((s) * 17408)
#define VS_OFF(s)  (34816 + (s) * 18432)
#define PS_OFF     71680
#define FLASH_SMEM_BYTES (PS_OFF + 128 * PP * 4)   // 106496
#define SC2 0.1803368801f   // (1/sqrt(64)) * log2(e)

__global__ __launch_bounds__(256)
void flash_tf32(const float* __restrict__ qkv, float* __restrict__ out)
{
    extern __shared__ char sm[];
    const uint32_t sb = smem_u32(sm);
    const int tid = threadIdx.x, w = tid >> 5, lane = tid & 31;
    const int g = lane >> 2, l4 = lane & 3;
    const int qt = (int)(gridDim.x - 1) - (int)blockIdx.x;
    const int hh = blockIdx.y, b = blockIdx.z;
    const int q0 = qt * FQT;
    const int nkv = 2 * qt + 2;

    const float* qg = qkv + (long)b * SEQ * QKV3 + hh * HDIM;
    const float* kg = qg + HID;
    const float* vg = qg + 2 * HID;

    {
        const int r = tid >> 1, h2 = tid & 1;
        const float* src = qg + (long)(q0 + r) * QKV3 + h2 * 32;
        uint32_t dst = sb + PS_OFF + (uint32_t)(r * PP + h2 * 32) * 4;
        #pragma unroll
        for (int q = 0; q < 8; q++) cp16(dst + q * 16, src + q * 4);
        cp_commit();
    }
    cp_wait0();
    __syncthreads();

    uint32_t qa[8][4];
    #pragma unroll
    for (int ks = 0; ks < 8; ks++) {
        uint32_t base = sb + PS_OFF
            + (uint32_t)((w * 16 + g) * PP + ks * 8 + l4) * 4;
        qa[ks][0] = ldsu(base);
        qa[ks][1] = ldsu(base + 8 * PP * 4);
        qa[ks][2] = ldsu(base + 16);
        qa[ks][3] = ldsu(base + 8 * PP * 4 + 16);
    }
    __syncthreads();

    auto issue_kv = [&](int kt2, int s) {
        const int k0 = kt2 * FKT;
        const int r = tid >> 2, q4 = tid & 3;
        const float* ksrc = kg + (long)(k0 + r) * QKV3 + q4 * 16;
        uint32_t kdst = sb + KS_OFF(s) + (uint32_t)(r * KP + q4 * 16) * 4;
        #pragma unroll
        for (int q = 0; q < 4; q++) cp16(kdst + q * 16, ksrc + q * 4);
        const float* vsrc = vg + (long)(k0 + r) * QKV3 + q4 * 16;
        uint32_t vdst = sb + VS_OFF(s) + (uint32_t)(r * VP + q4 * 16) * 4;
        #pragma unroll
        for (int q = 0; q < 4; q++) cp16(vdst + q * 16, vsrc + q * 4);
    };

    issue_kv(0, 0); cp_commit();
    if (nkv > 1) issue_kv(1, 1);
    cp_commit();

    float mA = -1e30f, mB = -1e30f, lA = 0.f, lB = 0.f;
    float o[8][4];
    #pragma unroll
    for (int nt = 0; nt < 8; nt++)
        #pragma unroll
        for (int q = 0; q < 4; q++) o[nt][q] = 0.f;

    const int wrow0 = q0 + w * 16;

    #pragma unroll 1
    for (int kt = 0; kt < nkv; kt++) {
        const int s = kt & 1;
        if (kt + 2 < nkv) cp_wait1(); else cp_wait0();
        __syncthreads();

        const int k0 = kt * FKT;
        const bool active = (k0 <= wrow0 + 15);
        const bool needmask = (k0 + FKT - 1 > wrow0);

        if (active) {
            const uint32_t kb = sb + KS_OFF(s);
            const uint32_t vb = sb + VS_OFF(s);

            float cc[8][4];
            #pragma unroll
            for (int nt = 0; nt < 8; nt++)
                #pragma unroll
                for (int q = 0; q < 4; q++) cc[nt][q] = 0.f;

            #pragma unroll
            for (int ks = 0; ks < 8; ks++) {
                uint32_t bfr[8][2];
                #pragma unroll
                for (int nt = 0; nt < 8; nt++) {
                    uint32_t a = kb + (uint32_t)((nt * 8 + g) * KP + ks * 8 + l4) * 4;
                    bfr[nt][0] = ldsu(a);
                    bfr[nt][1] = ldsu(a + 16);
                }
                #pragma unroll
                for (int nt = 0; nt < 8; nt++)
                    mma_tf32(cc[nt], qa[ks], bfr[nt]);
            }

            const int rowA = wrow0 + g;
            if (needmask) {
                #pragma unroll
                for (int nt = 0; nt < 8; nt++) {
                    const int colb = k0 + nt * 8 + 2 * l4;
                    if (colb     > rowA)     cc[nt][0] = -1e30f;
                    if (colb + 1 > rowA)     cc[nt][1] = -1e30f;
                    if (colb     > rowA + 8) cc[nt][2] = -1e30f;
                    if (colb + 1 > rowA + 8) cc[nt][3] = -1e30f;
                }
            }

            float mxA = -1e30f, mxB = -1e30f;
            #pragma unroll
            for (int nt = 0; nt < 8; nt++) {
                mxA = fmaxf(mxA, fmaxf(cc[nt][0], cc[nt][1]));
                mxB = fmaxf(mxB, fmaxf(cc[nt][2], cc[nt][3]));
            }
            mxA = fmaxf(mxA, __shfl_xor_sync(0xffffffffu, mxA, 1));
            mxA = fmaxf(mxA, __shfl_xor_sync(0xffffffffu, mxA, 2));
            mxB = fmaxf(mxB, __shfl_xor_sync(0xffffffffu, mxB, 1));
            mxB = fmaxf(mxB, __shfl_xor_sync(0xffffffffu, mxB, 2));

            const float mAn = fmaxf(mA, mxA);
            const float mBn = fmaxf(mB, mxB);
            const float aAl = ex2f((mA - mAn) * SC2);
            const float aBl = ex2f((mB - mBn) * SC2);
            mA = mAn; mB = mBn;

            float sA = 0.f, sB = 0.f;
            const uint32_t pbase = sb + PS_OFF
                + (uint32_t)((w * 16 + g) * PP + 2 * l4) * 4;
            #pragma unroll
            for (int nt = 0; nt < 8; nt++) {
                float p0 = ex2f((cc[nt][0] - mAn) * SC2);
                float p1 = ex2f((cc[nt][1] - mAn) * SC2);
                float p2 = ex2f((cc[nt][2] - mBn) * SC2);
                float p3 = ex2f((cc[nt][3] - mBn) * SC2);
                sA += p0 + p1; sB += p2 + p3;
                sts2(pbase + nt * 32, cvt_tf32(p0), cvt_tf32(p1));
                sts2(pbase + nt * 32 + 8 * PP * 4, cvt_tf32(p2), cvt_tf32(p3));
            }
            sA += __shfl_xor_sync(0xffffffffu, sA, 1);
            sA += __shfl_xor_sync(0xffffffffu, sA, 2);
            sB += __shfl_xor_sync(0xffffffffu, sB, 1);
            sB += __shfl_xor_sync(0xffffffffu, sB, 2);
            lA = lA * aAl + sA;
            lB = lB * aBl + sB;

            #pragma unroll
            for (int nt = 0; nt < 8; nt++) {
                o[nt][0] *= aAl; o[nt][1] *= aAl;
                o[nt][2] *= aBl; o[nt][3] *= aBl;
            }
            __syncwarp();

            #pragma unroll
            for (int ks = 0; ks < 8; ks++) {
                uint32_t pa[4];
                {
                    uint32_t base = sb + PS_OFF
                        + (uint32_t)((w * 16 + g) * PP + ks * 8 + l4) * 4;
                    pa[0] = ldsu(base);
                    pa[1] = ldsu(base + 8 * PP * 4);
                    pa[2] = ldsu(base + 16);
                    pa[3] = ldsu(base + 8 * PP * 4 + 16);
                }
                uint32_t bv[8][2];
                #pragma unroll
                for (int nt = 0; nt < 8; nt++) {
                    uint32_t a = vb + (uint32_t)((ks * 8 + l4) * VP + nt * 8 + g) * 4;
                    bv[nt][0] = ldsu(a);
                    bv[nt][1] = ldsu(a + 4 * VP * 4);
                }
                #pragma unroll
                for (int nt = 0; nt < 8; nt++)
                    mma_tf32(o[nt], pa, bv[nt]);
            }
        }

        __syncthreads();
        if (kt + 2 < nkv) { issue_kv(kt + 2, s); cp_commit(); }
    }

    {
        const float invA = 1.f / lA;
        const float invB = 1.f / lB;
        const long rowA = (long)b * SEQ + q0 + w * 16 + g;
        #pragma unroll
        for (int nt = 0; nt < 8; nt++) {
            const int col = hh * HDIM + nt * 8 + 2 * l4;
            *(float2*)&out[rowA * HID + col] =
                make_float2(cvt_tf32(o[nt][0] * invA), cvt_tf32(o[nt][1] * invA));
            *(float2*)&out[(rowA + 8) * HID + col] =
                make_float2(cvt_tf32(o[nt][2] * invB), cvt_tf32(o[nt][3] * invB));
        }
    }
}

// ---------------------------------------------------------------------------
// Launch
// ---------------------------------------------------------------------------
extern "C" void kernel_launch(void* const* d_in, const int* in_sizes, int n_in,
                              void* d_out, int out_size)
{
    const float* x     = (const float*)d_in[0];
    const float* w_qkv = (const float*)d_in[1];
    const float* w_out = (const float*)d_in[2];
    float* out = (float*)d_out;

    float *qkv, *attn, *xc, *wqkvT, *woutT;
    cudaGetSymbolAddress((void**)&qkv, g_qkv);
    cudaGetSymbolAddress((void**)&attn, g_attn);
    cudaGetSymbolAddress((void**)&xc, g_xc);
    cudaGetSymbolAddress((void**)&wqkvT, g_wqkvT);
    cudaGetSymbolAddress((void**)&woutT, g_woutT);

    const int M = BATCH * SEQ;   // 8192

    // 0) prep: tf32-round x; transpose+round weights to [N][K]
    {
        int n4 = (M * HID) / 4;
        cvt_tf32_kernel<<<(n4 + 255) / 256, 256>>>(x, xc, n4);
        transpose_tf32<<<dim3(QKV3 / 32, KDIM / 32), dim3(32, 8)>>>(w_qkv, wqkvT,
                                                                    KDIM, QKV3);
        transpose_tf32<<<dim3(HID / 32, KDIM / 32), dim3(32, 8)>>>(w_out, woutT,
                                                                   KDIM, HID);
    }

    cudaFuncSetAttribute(gemm_tf32<true>, cudaFuncAttributeMaxDynamicSharedMemorySize,
                         GEMM_SMEM_BYTES);
    cudaFuncSetAttribute(gemm_tf32<false>, cudaFuncAttributeMaxDynamicSharedMemorySize,
                         GEMM_SMEM_BYTES);
    cudaFuncSetAttribute(flash_tf32, cudaFuncAttributeMaxDynamicSharedMemorySize,
                         FLASH_SMEM_BYTES);

    // 1) QKV projection
    gemm_tf32<true><<<dim3(QKV3 / 128, M / 128), 256, GEMM_SMEM_BYTES>>>(
        xc, wqkvT, qkv, M, QKV3, KDIM);

    // 2) Causal flash attention
    flash_tf32<<<dim3(SEQ / FQT, NHEAD, BATCH), 256, FLASH_SMEM_BYTES>>>(qkv, attn);

    // 3) Output projection
    gemm_tf32<false><<<dim3(HID / 128, M / 128), 256, GEMM_SMEM_BYTES>>>(
        attn, woutT, out, M, HID, KDIM);
}

// round 11
// speedup vs baseline: 1.1365x; 1.0336x over previous
#include <cuda_runtime.h>
#include <cuda_bf16.h>
#include <cstdint>

// Problem constants
#define BATCH 4
#define SEQ   2048
#define HID   768
#define NHEAD 12
#define HDIM  64
#define QKV3  2304
#define KDIM  768

// Scratch (allocation-free: __device__ globals)
__device__ float g_qkv[(long)BATCH * SEQ * QKV3];    // [B,S,3H] tf32-rounded
__device__ float g_attn[(long)BATCH * SEQ * HID];    // [B,S,H]  tf32-rounded
__device__ float g_xc[(long)BATCH * SEQ * HID];      // x, tf32-rounded
__device__ float g_wqkvT[(long)QKV3 * KDIM];         // w_qkv tf32-rounded, [N][K]
__device__ float g_woutT[(long)HID * KDIM];          // w_out tf32-rounded, [N][K]
__device__ float g_vt[(long)BATCH * NHEAD * HDIM * SEQ];  // V transposed [b][h][d][s]

// ---------------------------------------------------------------------------
// Helpers
// ---------------------------------------------------------------------------
__device__ __forceinline__ uint32_t smem_u32(const void* p) {
    uint32_t a;
    asm("{ .reg .u64 t; cvta.to.shared.u64 t, %1; cvt.u32.u64 %0, t; }" : "=r"(a) : "l"(p));
    return a;
}
__device__ __forceinline__ float cvt_tf32(float x) {
    float r;
    asm("cvt.rna.tf32.f32 %0, %1;" : "=f"(r) : "f"(x));
    return r;
}
__device__ __forceinline__ float ex2f(float x) {
    float r;
    asm("ex2.approx.f32 %0, %1;" : "=f"(r) : "f"(x));
    return r;
}
__device__ __forceinline__ void cp16(uint32_t dst, const void* src) {
    asm volatile("cp.async.cg.shared.global [%0], [%1], 16;" :: "r"(dst), "l"(src) : "memory");
}
__device__ __forceinline__ void cp_commit() {
    asm volatile("cp.async.commit_group;" ::: "memory");
}
__device__ __forceinline__ void cp_wait1() {
    asm volatile("cp.async.wait_group 1;" ::: "memory");
}
__device__ __forceinline__ void cp_wait0() {
    asm volatile("cp.async.wait_group 0;" ::: "memory");
}
__device__ __forceinline__ uint32_t ldsu(uint32_t addr) {
    uint32_t v;
    asm volatile("ld.shared.b32 %0, [%1];" : "=r"(v) : "r"(addr));
    return v;
}
__device__ __forceinline__ void sts2(uint32_t addr, float x, float y) {
    asm volatile("st.shared.v2.f32 [%0], {%1, %2};" :: "r"(addr), "f"(x), "f"(y) : "memory");
}
__device__ __forceinline__ void ldsm4(uint32_t* r, uint32_t addr) {
    asm volatile("ldmatrix.sync.aligned.m8n8.x4.shared.b16 {%0,%1,%2,%3}, [%4];"
                 : "=r"(r[0]), "=r"(r[1]), "=r"(r[2]), "=r"(r[3]) : "r"(addr));
}
__device__ __forceinline__ void ldsm2(uint32_t* r, uint32_t addr) {
    asm volatile("ldmatrix.sync.aligned.m8n8.x2.shared.b16 {%0,%1}, [%2];"
                 : "=r"(r[0]), "=r"(r[1]) : "r"(addr));
}
__device__ __forceinline__ void mma_tf32(float* c, const uint32_t* a, const uint32_t* b) {
    asm volatile(
        "mma.sync.aligned.m16n8k8.row.col.f32.tf32.tf32.f32 "
        "{%0,%1,%2,%3}, {%4,%5,%6,%7}, {%8,%9}, {%0,%1,%2,%3};"
        : "+f"(c[0]), "+f"(c[1]), "+f"(c[2]), "+f"(c[3])
        : "r"(a[0]), "r"(a[1]), "r"(a[2]), "r"(a[3]), "r"(b[0]), "r"(b[1]));
}

// ---------------------------------------------------------------------------
// tf32 mma.sync GEMM v4 (R10, passing, unchanged): ldmatrix fragment loads.
// C[M,N] = A[M,K] @ Bt[N,K]^T.  CTA 128x128, K chunk 32, 3-stage cp.async.
// ---------------------------------------------------------------------------
#define AT_BYTES (128 * 36 * 4)   // 18432
#define STAGE_BYTES (2 * AT_BYTES)
#define GEMM_SMEM_BYTES (3 * STAGE_BYTES)   // 110592

template <bool ROUND>
__global__ __launch_bounds__(256, 2)
void gemm_tf32(const float* __restrict__ A, const float* __restrict__ Bt,
               float* __restrict__ C, int M, int N, int K)
{
    extern __shared__ char smem[];
    const uint32_t sb = smem_u32(smem);

    const int tid = threadIdx.x;
    const int wid = tid >> 5, lane = tid & 31;
    const int g = lane >> 2, l4 = lane & 3;
    const int warpM = wid >> 2, warpN = wid & 3;
    const int m0 = blockIdx.y * 128, n0 = blockIdx.x * 128;

    const int r = tid >> 1;
    const int h = (tid & 1) * 64;

    const float* Ag = A + (long)(m0 + r) * K + (h >> 2);
    const float* Bg = Bt + (long)(n0 + r) * K + (h >> 2);
    const int nch = K / 32;

    float c[4][4][4];
    #pragma unroll
    for (int mt = 0; mt < 4; mt++)
        #pragma unroll
        for (int nt = 0; nt < 4; nt++)
            #pragma unroll
            for (int q = 0; q < 4; q++) c[mt][nt][q] = 0.f;

    auto issue = [&](int chunk, int s) {
        const int k0 = chunk * 32;
        const uint32_t stage = sb + (uint32_t)s * STAGE_BYTES;
        const uint32_t dst = stage + r * 144 + h;
        const float* asrc = Ag + k0;
        #pragma unroll
        for (int q = 0; q < 4; q++) cp16(dst + q * 16, asrc + q * 4);
        const float* bsrc = Bg + k0;
        #pragma unroll
        for (int q = 0; q < 4; q++) cp16(dst + AT_BYTES + q * 16, bsrc + q * 4);
    };

    issue(0, 0); cp_commit();
    issue(1, 1); cp_commit();

    const int rlm = lane & 15, half = (lane >> 4) * 16;
    const int nr = lane & 7, sel = ((lane >> 3) & 1) * 16;
    const uint32_t aoff = (uint32_t)((warpM * 64 + rlm) * 144 + half);
    const uint32_t boff = (uint32_t)(AT_BYTES + (warpN * 32 + nr) * 144 + sel);

    #pragma unroll 1
    for (int i = 0; i < nch; i++) {
        const int s = i - (i / 3) * 3;
        if (i + 1 < nch) cp_wait1(); else cp_wait0();
        __syncthreads();
        if (i + 2 < nch) { issue(i + 2, (i + 2) % 3); cp_commit(); }

        const uint32_t abase = sb + (uint32_t)s * STAGE_BYTES + aoff;
        const uint32_t bbase = sb + (uint32_t)s * STAGE_BYTES + boff;

        #pragma unroll
        for (int ks = 0; ks < 4; ks++) {
            uint32_t af[4][4], bf[4][2];
            #pragma unroll
            for (int mt = 0; mt < 4; mt++)
                ldsm4(af[mt], abase + mt * (16 * 144) + ks * 32);
            #pragma unroll
            for (int nt = 0; nt < 4; nt++)
                ldsm2(bf[nt], bbase + nt * (8 * 144) + ks * 32);
            #pragma unroll
            for (int mt = 0; mt < 4; mt++)
                #pragma unroll
                for (int nt = 0; nt < 4; nt++)
                    mma_tf32(c[mt][nt], af[mt], bf[nt]);
        }
    }

    #pragma unroll
    for (int mt = 0; mt < 4; mt++) {
        #pragma unroll
        for (int nt = 0; nt < 4; nt++) {
            const long row0 = (long)(m0 + warpM * 64 + mt * 16 + g);
            const int col = n0 + warpN * 32 + nt * 8 + l4 * 2;
            float v0 = c[mt][nt][0], v1 = c[mt][nt][1];
            float v2 = c[mt][nt][2], v3 = c[mt][nt][3];
            if (ROUND) {
                v0 = cvt_tf32(v0); v1 = cvt_tf32(v1);
                v2 = cvt_tf32(v2); v3 = cvt_tf32(v3);
            }
            *(float2*)&C[row0 * N + col] = make_float2(v0, v1);
            *(float2*)&C[(row0 + 8) * N + col] = make_float2(v2, v3);
        }
    }
}

// ---------------------------------------------------------------------------
// Prep kernels
// ---------------------------------------------------------------------------
__global__ void cvt_tf32_kernel(const float* __restrict__ in, float* __restrict__ out,
                                int n4)
{
    int i = blockIdx.x * blockDim.x + threadIdx.x;
    if (i < n4) {
        float4 v = ((const float4*)in)[i];
        v.x = cvt_tf32(v.x); v.y = cvt_tf32(v.y);
        v.z = cvt_tf32(v.z); v.w = cvt_tf32(v.w);
        ((float4*)out)[i] = v;
    }
}

// out[c][r] = tf32(in[r][c]).  in: [R][C] row-major, out: [C][R] row-major.
__global__ void transpose_tf32(const float* __restrict__ in, float* __restrict__ out,
                               int R, int C)
{
    __shared__ float tile[32][33];
    const int c0 = blockIdx.x * 32, r0 = blockIdx.y * 32;
    const int tx = threadIdx.x, ty = threadIdx.y;
    #pragma unroll
    for (int j = ty; j < 32; j += 8)
        tile[j][tx] = in[(long)(r0 + j) * C + c0 + tx];
    __syncthreads();
    #pragma unroll
    for (int j = ty; j < 32; j += 8)
        out[(long)(c0 + j) * R + r0 + tx] = cvt_tf32(tile[tx][j]);
}

// V slice of qkv -> vt[b][h][d][s]  (values already tf32-rounded)
__global__ void transpose_v(const float* __restrict__ qkv, float* __restrict__ vt)
{
    __shared__ float tile[32][33];
    const int bh = blockIdx.z;
    const int b = bh / NHEAD, hh = bh % NHEAD;
    const float* in = qkv + (long)b * SEQ * QKV3 + 2 * HID + hh * HDIM;
    float* out = vt + (long)bh * HDIM * SEQ;
    const int c0 = blockIdx.x * 32, r0 = blockIdx.y * 32;   // c: dim, r: seq
    const int tx = threadIdx.x, ty = threadIdx.y;
    #pragma unroll
    for (int j = ty; j < 32; j += 8)
        tile[j][tx] = in[(long)(r0 + j) * QKV3 + c0 + tx];
    __syncthreads();
    #pragma unroll
    for (int j = ty; j < 32; j += 8)
        out[(long)(c0 + j) * SEQ + r0 + tx] = tile[tx][j];
}

// ---------------------------------------------------------------------------
// Flash attention (causal) on tf32 mma.sync, v3: ldmatrix fragment loads.
// 256 threads / 8 warps; warp w owns 16 q-rows of the 128-row tile.
// K tile [64 keys][68f] (QK^T B via ldsm2); Vt tile [64 dims][68f] (PV B via
// ldsm2); P/Q staged [128][68f] (A-frags via ldsm4).
// All pitches 272B = 17x16B groups -> conflict-free ldmatrix phases.
// ---------------------------------------------------------------------------
#define FQT 128
#define FKT 64
#define KP 68
#define VP 68
#define PP 68
#define KS_OFF(s)  ((s) * 17408)
#define VS_OFF(s)  (34816 + (s) * 17408)
#define PS_OFF     69632
#define FLASH_SMEM_BYTES (PS_OFF + 128 * PP * 4)   // 104448
#define SC2 0.1803368801f   // (1/sqrt(64)) * log2(e)

__global__ __launch_bounds__(256)
void flash_tf32(const float* __restrict__ qkv, const float* __restrict__ vt,
                float* __restrict__ out)
{
    extern __shared__ char sm[];
    const uint32_t sb = smem_u32(sm);
    const int tid = threadIdx.x, w = tid >> 5, lane = tid & 31;
    const int g = lane >> 2, l4 = lane & 3;
    const int qt = (int)(gridDim.x - 1) - (int)blockIdx.x;
    const int hh = blockIdx.y, b = blockIdx.z;
    const int q0 = qt * FQT;
    const int nkv = 2 * qt + 2;

    const float* qg = qkv + (long)b * SEQ * QKV3 + hh * HDIM;
    const float* kg = qg + HID;
    const float* vtg = vt + (long)(b * NHEAD + hh) * HDIM * SEQ;

    // ldmatrix lane address components
    const int rlm = lane & 15, half = (lane >> 4) * 16;   // x4 (A frags)
    const int nr = lane & 7, sel = ((lane >> 3) & 1) * 16; // x2 (B frags)

    // --- Stage Q into PS region [128][PP] ---
    {
        const int r = tid >> 1, h2 = tid & 1;
        const float* src = qg + (long)(q0 + r) * QKV3 + h2 * 32;
        uint32_t dst = sb + PS_OFF + (uint32_t)(r * PP + h2 * 32) * 4;
        #pragma unroll
        for (int q = 0; q < 8; q++) cp16(dst + q * 16, src + q * 4);
        cp_commit();
    }
    cp_wait0();
    __syncthreads();

    // --- Q fragments via ldsm4: warp rows [w*16, w*16+16) ---
    uint32_t qa[8][4];
    #pragma unroll
    for (int ks = 0; ks < 8; ks++)
        ldsm4(qa[ks], sb + PS_OFF + (uint32_t)((w * 16 + rlm) * PP) * 4
                      + ks * 32 + half);
    __syncthreads();

    // KV loader: K [64 keys][68f] from kg rows; Vt [64 dims][68f] from vtg rows
    auto issue_kv = [&](int kt2, int s) {
        const int k0 = kt2 * FKT;
        const int r = tid >> 2, q4 = tid & 3;
        const float* ksrc = kg + (long)(k0 + r) * QKV3 + q4 * 16;
        uint32_t kdst = sb + KS_OFF(s) + (uint32_t)(r * KP + q4 * 16) * 4;
        #pragma unroll
        for (int q = 0; q < 4; q++) cp16(kdst + q * 16, ksrc + q * 4);
        const float* vsrc = vtg + (long)r * SEQ + k0 + q4 * 16;   // r = dim
        uint32_t vdst = sb + VS_OFF(s) + (uint32_t)(r * VP + q4 * 16) * 4;
        #pragma unroll
        for (int q = 0; q < 4; q++) cp16(vdst + q * 16, vsrc + q * 4);
    };

    issue_kv(0, 0); cp_commit();
    if (nkv > 1) issue_kv(1, 1);
    cp_commit();

    float mA = -1e30f, mB = -1e30f, lA = 0.f, lB = 0.f;
    float o[8][4];
    #pragma unroll
    for (int nt = 0; nt < 8; nt++)
        #pragma unroll
        for (int q = 0; q < 4; q++) o[nt][q] = 0.f;

    const int wrow0 = q0 + w * 16;

    #pragma unroll 1
    for (int kt = 0; kt < nkv; kt++) {
        const int s = kt & 1;
        if (kt + 2 < nkv) cp_wait1(); else cp_wait0();
        __syncthreads();

        const int k0 = kt * FKT;
        const bool active = (k0 <= wrow0 + 15);
        const bool needmask = (k0 + FKT - 1 > wrow0);

        if (active) {
            const uint32_t kb = sb + KS_OFF(s);
            const uint32_t vb = sb + VS_OFF(s);

            float cc[8][4];
            #pragma unroll
            for (int nt = 0; nt < 8; nt++)
                #pragma unroll
                for (int q = 0; q < 4; q++) cc[nt][q] = 0.f;

            // S = Q @ K^T : B-frags via ldsm2 from K [keys][dims]
            #pragma unroll
            for (int ks = 0; ks < 8; ks++) {
                uint32_t bfr[8][2];
                #pragma unroll
                for (int nt = 0; nt < 8; nt++)
                    ldsm2(bfr[nt], kb + (uint32_t)((nt * 8 + nr) * KP) * 4
                                   + ks * 32 + sel);
                #pragma unroll
                for (int nt = 0; nt < 8; nt++)
                    mma_tf32(cc[nt], qa[ks], bfr[nt]);
            }

            const int rowA = wrow0 + g;
            if (needmask) {
                #pragma unroll
                for (int nt = 0; nt < 8; nt++) {
                    const int colb = k0 + nt * 8 + 2 * l4;
                    if (colb     > rowA)     cc[nt][0] = -1e30f;
                    if (colb + 1 > rowA)     cc[nt][1] = -1e30f;
                    if (colb     > rowA + 8) cc[nt][2] = -1e30f;
                    if (colb + 1 > rowA + 8) cc[nt][3] = -1e30f;
                }
            }

            float mxA = -1e30f, mxB = -1e30f;
            #pragma unroll
            for (int nt = 0; nt < 8; nt++) {
                mxA = fmaxf(mxA, fmaxf(cc[nt][0], cc[nt][1]));
                mxB = fmaxf(mxB, fmaxf(cc[nt][2], cc[nt][3]));
            }
            mxA = fmaxf(mxA, __shfl_xor_sync(0xffffffffu, mxA, 1));
            mxA = fmaxf(mxA, __shfl_xor_sync(0xffffffffu, mxA, 2));
            mxB = fmaxf(mxB, __shfl_xor_sync(0xffffffffu, mxB, 1));
            mxB = fmaxf(mxB, __shfl_xor_sync(0xffffffffu, mxB, 2));

            const float mAn = fmaxf(mA, mxA);
            const float mBn = fmaxf(mB, mxB);
            const float aAl = ex2f((mA - mAn) * SC2);
            const float aBl = ex2f((mB - mBn) * SC2);
            mA = mAn; mB = mBn;

            float sA = 0.f, sB = 0.f;
            const uint32_t pbase = sb + PS_OFF
                + (uint32_t)((w * 16 + g) * PP + 2 * l4) * 4;
            #pragma unroll
            for (int nt = 0; nt < 8; nt++) {
                float p0 = ex2f((cc[nt][0] - mAn) * SC2);
                float p1 = ex2f((cc[nt][1] - mAn) * SC2);
                float p2 = ex2f((cc[nt][2] - mBn) * SC2);
                float p3 = ex2f((cc[nt][3] - mBn) * SC2);
                sA += p0 + p1; sB += p2 + p3;
                sts2(pbase + nt * 32, cvt_tf32(p0), cvt_tf32(p1));
                sts2(pbase + nt * 32 + 8 * PP * 4, cvt_tf32(p2), cvt_tf32(p3));
            }
            sA += __shfl_xor_sync(0xffffffffu, sA, 1);
            sA += __shfl_xor_sync(0xffffffffu, sA, 2);
            sB += __shfl_xor_sync(0xffffffffu, sB, 1);
            sB += __shfl_xor_sync(0xffffffffu, sB, 2);
            lA = lA * aAl + sA;
            lB = lB * aBl + sB;

            #pragma unroll
            for (int nt = 0; nt < 8; nt++) {
                o[nt][0] *= aAl; o[nt][1] *= aAl;
                o[nt][2] *= aBl; o[nt][3] *= aBl;
            }
            __syncwarp();

            // O += P @ V : A-frags ldsm4 from P, B-frags ldsm2 from Vt [dims][keys]
            #pragma unroll
            for (int ks = 0; ks < 8; ks++) {
                uint32_t pa[4];
                ldsm4(pa, sb + PS_OFF + (uint32_t)((w * 16 + rlm) * PP) * 4
                          + ks * 32 + half);
                uint32_t bv[8][2];
                #pragma unroll
                for (int nt = 0; nt < 8; nt++)
                    ldsm2(bv[nt], vb + (uint32_t)((nt * 8 + nr) * VP) * 4
                                  + ks * 32 + sel);
                #pragma unroll
                for (int nt = 0; nt < 8; nt++)
                    mma_tf32(o[nt], pa, bv[nt]);
            }
        }

        __syncthreads();
        if (kt + 2 < nkv) { issue_kv(kt + 2, s); cp_commit(); }
    }

    {
        const float invA = 1.f / lA;
        const float invB = 1.f / lB;
        const long rowA = (long)b * SEQ + q0 + w * 16 + g;
        #pragma unroll
        for (int nt = 0; nt < 8; nt++) {
            const int col = hh * HDIM + nt * 8 + 2 * l4;
            *(float2*)&out[rowA * HID + col] =
                make_float2(cvt_tf32(o[nt][0] * invA), cvt_tf32(o[nt][1] * invA));
            *(float2*)&out[(rowA + 8) * HID + col] =
                make_float2(cvt_tf32(o[nt][2] * invB), cvt_tf32(o[nt][3] * invB));
        }
    }
}

// ---------------------------------------------------------------------------
// Launch
// ---------------------------------------------------------------------------
extern "C" void kernel_launch(void* const* d_in, const int* in_sizes, int n_in,
                              void* d_out, int out_size)
{
    const float* x     = (const float*)d_in[0];
    const float* w_qkv = (const float*)d_in[1];
    const float* w_out = (const float*)d_in[2];
    float* out = (float*)d_out;

    float *qkv, *attn, *xc, *wqkvT, *woutT, *vt;
    cudaGetSymbolAddress((void**)&qkv, g_qkv);
    cudaGetSymbolAddress((void**)&attn, g_attn);
    cudaGetSymbolAddress((void**)&xc, g_xc);
    cudaGetSymbolAddress((void**)&wqkvT, g_wqkvT);
    cudaGetSymbolAddress((void**)&woutT, g_woutT);
    cudaGetSymbolAddress((void**)&vt, g_vt);

    const int M = BATCH * SEQ;   // 8192

    // 0) prep: tf32-round x; transpose+round weights to [N][K]
    {
        int n4 = (M * HID) / 4;
        cvt_tf32_kernel<<<(n4 + 255) / 256, 256>>>(x, xc, n4);
        transpose_tf32<<<dim3(QKV3 / 32, KDIM / 32), dim3(32, 8)>>>(w_qkv, wqkvT,
                                                                    KDIM, QKV3);
        transpose_tf32<<<dim3(HID / 32, KDIM / 32), dim3(32, 8)>>>(w_out, woutT,
                                                                   KDIM, HID);
    }

    cudaFuncSetAttribute(gemm_tf32<true>, cudaFuncAttributeMaxDynamicSharedMemorySize,
                         GEMM_SMEM_BYTES);
    cudaFuncSetAttribute(gemm_tf32<false>, cudaFuncAttributeMaxDynamicSharedMemorySize,
                         GEMM_SMEM_BYTES);
    cudaFuncSetAttribute(flash_tf32, cudaFuncAttributeMaxDynamicSharedMemorySize,
                         FLASH_SMEM_BYTES);

    // 1) QKV projection
    gemm_tf32<true><<<dim3(QKV3 / 128, M / 128), 256, GEMM_SMEM_BYTES>>>(
        xc, wqkvT, qkv, M, QKV3, KDIM);

    // 1b) V -> vt[b][h][d][s]
    transpose_v<<<dim3(HDIM / 32, SEQ / 32, BATCH * NHEAD), dim3(32, 8)>>>(qkv, vt);

    // 2) Causal flash attention
    flash_tf32<<<dim3(SEQ / FQT, NHEAD, BATCH), 256, FLASH_SMEM_BYTES>>>(qkv, vt, attn);

    // 3) Output projection
    gemm_tf32<false><<<dim3(HID / 128, M / 128), 256, GEMM_SMEM_BYTES>>>(
        attn, woutT, out, M, HID, KDIM);
}